// round 13
// baseline (speedup 1.0000x reference)
#include <cuda_runtime.h>
#include <cuda_fp16.h>
#include <math.h>
#include <stdint.h>

#define BB 2
#define NN 2048
#define EE 1024
#define HH 8
#define DD 64
#define MM (BB*NN)
#define N3 (3*EE)

typedef __half fp16;

// ---------------- scratch (__device__ globals; no runtime alloc) ----------------
__device__ fp16 g_wqkvh[(size_t)EE * N3];   // [k=1024][n=3072] hi  (Wq|Wk|Wv)
__device__ fp16 g_wqkvl[(size_t)EE * N3];   // lo
__device__ fp16 g_woh[(size_t)EE * EE], g_wol[(size_t)EE * EE];
__device__ fp16 g_x16[MM * EE];
__device__ fp16 g_q[MM * EE];               // single-rounded q (alpha pre-applied)
__device__ fp16 g_k[MM * EE];
__device__ fp16 g_v[MM * EE];
__device__ fp16 g_a16[MM * EE];
__device__ float g_lambda;

// ---------------- helpers ----------------
__device__ __forceinline__ uint32_t s2u(const void* p) {
    return (uint32_t)__cvta_generic_to_shared(p);
}
__device__ __forceinline__ void ldsm4(uint32_t* r, uint32_t a) {
    asm volatile("ldmatrix.sync.aligned.m8n8.x4.shared.b16 {%0,%1,%2,%3},[%4];\n"
                 : "=r"(r[0]), "=r"(r[1]), "=r"(r[2]), "=r"(r[3]) : "r"(a));
}
__device__ __forceinline__ void ldsm4t(uint32_t* r, uint32_t a) {
    asm volatile("ldmatrix.sync.aligned.m8n8.x4.trans.shared.b16 {%0,%1,%2,%3},[%4];\n"
                 : "=r"(r[0]), "=r"(r[1]), "=r"(r[2]), "=r"(r[3]) : "r"(a));
}
__device__ __forceinline__ void mma16816(float* d, const uint32_t* a, uint32_t b0, uint32_t b1) {
    asm volatile("mma.sync.aligned.m16n8k16.row.col.f32.f16.f16.f32 "
                 "{%0,%1,%2,%3},{%4,%5,%6,%7},{%8,%9},{%0,%1,%2,%3};\n"
                 : "+f"(d[0]), "+f"(d[1]), "+f"(d[2]), "+f"(d[3])
                 : "r"(a[0]), "r"(a[1]), "r"(a[2]), "r"(a[3]), "r"(b0), "r"(b1));
}
__device__ __forceinline__ void cpa16(uint32_t dst, const void* src) {
    asm volatile("cp.async.cg.shared.global [%0], [%1], 16;\n" :: "r"(dst), "l"(src));
}
#define CP_COMMIT asm volatile("cp.async.commit_group;\n")
#define CP_WAIT0  asm volatile("cp.async.wait_group 0;\n")
#define CP_WAIT1  asm volatile("cp.async.wait_group 1;\n")
__device__ __forceinline__ float ex2(float x) {
    float y; asm("ex2.approx.f32 %0,%1;\n" : "=f"(y) : "f"(x)); return y;
}
// pack (a -> lo, b -> hi) to fp16x2 and take exp2 of both halves in one MUFU op
__device__ __forceinline__ uint32_t exp2pack(float a, float b) {
    uint32_t p;
    asm("cvt.rn.f16x2.f32 %0, %1, %2;\n" : "=r"(p) : "f"(b), "f"(a));
    asm("ex2.approx.f16x2 %0, %0;\n" : "+r"(p));
    return p;
}
__device__ __forceinline__ void split2h(float a, float b, uint32_t& hi, uint32_t& lo) {
    __half2 h, l;
    h.x = __float2half_rn(a); h.y = __float2half_rn(b);
    l.x = __float2half_rn(a - __half2float(h.x));
    l.y = __float2half_rn(b - __half2float(h.y));
    hi = *(uint32_t*)&h; lo = *(uint32_t*)&l;
}
__device__ __forceinline__ uint32_t pack2h(float a, float b) {
    __half2 h; h.x = __float2half_rn(a); h.y = __float2half_rn(b);
    return *(uint32_t*)&h;
}

// ---------------- lambda ----------------
__global__ void lambda_kernel(const float* __restrict__ lq1, const float* __restrict__ lk1,
                              const float* __restrict__ lq2, const float* __restrict__ lk2) {
    int t = threadIdx.x;
    float s1 = 0.f, s2 = 0.f;
    for (int i = t; i < DD; i += 32) { s1 += lq1[i] * lk1[i]; s2 += lq2[i] * lk2[i]; }
#pragma unroll
    for (int o = 16; o; o >>= 1) {
        s1 += __shfl_xor_sync(0xffffffffu, s1, o);
        s2 += __shfl_xor_sync(0xffffffffu, s2, o);
    }
    if (t == 0) {
        double lam_init = 0.8 - 0.6 * exp(-0.3 * 12.0);
        g_lambda = expf(s1) - expf(s2) + (float)lam_init;
    }
}

// ---------------- weight split: Wq|Wk|Wv -> fused [1024][3072] pair; Wo -> [1024][1024] pair ----------------
__global__ void wsplit_kernel(const float* __restrict__ W0, const float* __restrict__ W1,
                              const float* __restrict__ W2, const float* __restrict__ W3) {
    int m = blockIdx.y;  // 0..3
    const float* W = (m == 0) ? W0 : (m == 1) ? W1 : (m == 2) ? W2 : W3;
    size_t i = (size_t)blockIdx.x * 1024 + threadIdx.x * 4;
    float4 v = *(const float4*)&W[i];
    uint32_t h0, l0, h1, l1;
    split2h(v.x, v.y, h0, l0);
    split2h(v.z, v.w, h1, l1);
    size_t r = i >> 10, c = i & 1023;
    uint32_t *oh, *ol;
    if (m < 3) {
        size_t d = r * N3 + m * EE + c;
        oh = (uint32_t*)&g_wqkvh[d]; ol = (uint32_t*)&g_wqkvl[d];
    } else {
        oh = (uint32_t*)&g_woh[i]; ol = (uint32_t*)&g_wol[i];
    }
    oh[0] = h0; oh[1] = h1; ol[0] = l0; ol[1] = l1;
}

__global__ void xround_kernel(const float* __restrict__ x) {
    size_t i = (size_t)blockIdx.x * 1024 + threadIdx.x * 4;
    float4 v = *(const float4*)&x[i];
    uint32_t* o = (uint32_t*)&g_x16[i];
    o[0] = pack2h(v.x, v.y);
    o[1] = pack2h(v.z, v.w);
}

// ============ shared GEMM mainloop (BK=64, 128x128 CTA tile, 2-term weights) ============
// Single-barrier pipeline: wait_group 0 -> sync -> issue next copy -> compute.
// smem layout (fp16 elems), per buf (stride 26624): A 128x64 pitch 72 at +0 (9216),
// Bh 64x128 pitch 136 at +9216 (8704), Bl at +17920 (8704). 2 bufs = 53248 elems.
#define GSM_ELEMS 53248
#define GSM_BYTES (GSM_ELEMS * 2)

#define GEMM_MAINLOOP(LDW)                                                                   \
    float acc[4][4][4];                                                                       \
    _Pragma("unroll") for (int i = 0; i < 4; ++i)                                             \
        _Pragma("unroll") for (int j = 0; j < 4; ++j)                                         \
            _Pragma("unroll") for (int q = 0; q < 4; ++q) acc[i][j][q] = 0.f;                 \
    auto copy_tile = [&](int kt, int bu) {                                                    \
        int base = bu * 26624;                                                                \
        _Pragma("unroll") for (int j = 0; j < 4; ++j) {                                       \
            int ch = tid + j * 256;                                                           \
            int r = ch >> 3, s = (ch & 7) * 8;                                                \
            cpa16(s2u(&sg[base + r * 72 + s]), &A[(size_t)(m0 + r) * EE + kt + s]);           \
        }                                                                                     \
        _Pragma("unroll") for (int j = 0; j < 4; ++j) {                                       \
            int ch = tid + j * 256;                                                           \
            int r = ch >> 4, s = (ch & 15) * 8;                                               \
            cpa16(s2u(&sg[base + 9216 + r * 136 + s]), &Wh[(size_t)(kt + r) * (LDW) + n0 + s]); \
            cpa16(s2u(&sg[base + 17920 + r * 136 + s]), &Wl[(size_t)(kt + r) * (LDW) + n0 + s]); \
        }                                                                                     \
    };                                                                                        \
    copy_tile(0, 0);                                                                          \
    CP_COMMIT;                                                                                \
    int bu = 0;                                                                               \
    for (int kt = 0; kt < EE; kt += 64, bu ^= 1) {                                            \
        CP_WAIT0;                                                                             \
        __syncthreads();                                                                      \
        if (kt + 64 < EE) copy_tile(kt + 64, bu ^ 1);                                         \
        CP_COMMIT;                                                                            \
        int ao = bu * 26624, bo = ao + 9216;                                                  \
        _Pragma("unroll") for (int kg = 0; kg < 4; ++kg) {                                    \
            uint32_t ah[4][4], bh[4][2], bl[4][2];                                            \
            _Pragma("unroll") for (int i = 0; i < 4; ++i) {                                   \
                int off = (wm + i * 16 + (lane & 15)) * 72 + kg * 16 + (lane >> 4) * 8;       \
                ldsm4(ah[i], s2u(&sg[ao + off]));                                             \
            }                                                                                 \
            _Pragma("unroll") for (int p = 0; p < 2; ++p) {                                   \
                int off = (kg * 16 + (lane & 15)) * 136 + wn + p * 16 + (lane >> 4) * 8;      \
                uint32_t t[4], u[4];                                                          \
                ldsm4t(t, s2u(&sg[bo + off]));                                                \
                ldsm4t(u, s2u(&sg[bo + 8704 + off]));                                         \
                bh[2 * p][0] = t[0]; bh[2 * p][1] = t[1];                                     \
                bh[2 * p + 1][0] = t[2]; bh[2 * p + 1][1] = t[3];                             \
                bl[2 * p][0] = u[0]; bl[2 * p][1] = u[1];                                     \
                bl[2 * p + 1][0] = u[2]; bl[2 * p + 1][1] = u[3];                             \
            }                                                                                 \
            _Pragma("unroll") for (int i = 0; i < 4; ++i)                                     \
                _Pragma("unroll") for (int ni = 0; ni < 4; ++ni) {                            \
                    mma16816(acc[i][ni], ah[i], bh[ni][0], bh[ni][1]);                        \
                    mma16816(acc[i][ni], ah[i], bl[ni][0], bl[ni][1]);                        \
                }                                                                             \
        }                                                                                     \
    }

// ---------------- fused QKV GEMM: C[4096,3072] = x16 @ (Wh+Wl); all outputs single fp16 ----------------
__global__ __launch_bounds__(256, 2) void qkv_gemm(const fp16* __restrict__ A,
                                                   const fp16* __restrict__ Wh, const fp16* __restrict__ Wl,
                                                   fp16* __restrict__ Q, fp16* __restrict__ K,
                                                   fp16* __restrict__ V, float alpha_q) {
    extern __shared__ fp16 sg[];
    const int tid = threadIdx.x, lane = tid & 31, wid = tid >> 5;
    const int wm = (wid >> 2) * 64, wn = (wid & 3) * 32;
    const int m0 = blockIdx.y * 128, n0 = blockIdx.x * 128;

    GEMM_MAINLOOP(N3)

    const int sec = blockIdx.x >> 3;               // 0=q, 1=k, 2=v
    const int nbase = n0 - sec * EE;
    fp16* dst = (sec == 0) ? Q : (sec == 1) ? K : V;
    const float al = (sec == 0) ? alpha_q : 1.f;
#pragma unroll
    for (int mi = 0; mi < 4; ++mi) {
        int r0 = m0 + wm + mi * 16 + (lane >> 2);
        int r1 = r0 + 8;
#pragma unroll
        for (int ni = 0; ni < 4; ++ni) {
            int col = nbase + wn + ni * 8 + 2 * (lane & 3);
            *(uint32_t*)&dst[(size_t)r0 * EE + col] = pack2h(acc[mi][ni][0] * al, acc[mi][ni][1] * al);
            *(uint32_t*)&dst[(size_t)r1 * EE + col] = pack2h(acc[mi][ni][2] * al, acc[mi][ni][3] * al);
        }
    }
}

// ---------------- output GEMM: out[4096,1024] fp32 = a16 @ (Woh+Wol) ----------------
__global__ __launch_bounds__(256, 2) void out_gemm(const fp16* __restrict__ A,
                                                   const fp16* __restrict__ Wh, const fp16* __restrict__ Wl,
                                                   float* __restrict__ Cf) {
    extern __shared__ fp16 sg[];
    const int tid = threadIdx.x, lane = tid & 31, wid = tid >> 5;
    const int wm = (wid >> 2) * 64, wn = (wid & 3) * 32;
    const int m0 = blockIdx.y * 128, n0 = blockIdx.x * 128;

    GEMM_MAINLOOP(EE)

#pragma unroll
    for (int mi = 0; mi < 4; ++mi) {
        int r0 = m0 + wm + mi * 16 + (lane >> 2);
        int r1 = r0 + 8;
#pragma unroll
        for (int ni = 0; ni < 4; ++ni) {
            int col = n0 + wn + ni * 8 + 2 * (lane & 3);
            *(float2*)&Cf[(size_t)r0 * EE + col] = make_float2(acc[mi][ni][0], acc[mi][ni][1]);
            *(float2*)&Cf[(size_t)r1 * EE + col] = make_float2(acc[mi][ni][2], acc[mi][ni][3]);
        }
    }
}

// ---------------- differential flash attention + fused LayerNorm (64-key tiles) ----------------
// CTA: (64 q-rows, head-pair hp, batch b); 4 warps x 16 rows; 64-key tiles double-buffered,
// single barrier per tile; Q fragments hoisted to registers; warp-voted rescale skip.
// smem (fp16 elems): Q 0 (64x136=8704); KV buf b at 8704+b*17408: K +0, V +8704.
#define SQ 0
#define KVB 8704
#define FSM_ELEMS (8704 + 2 * 17408)
#define FSM_BYTES (FSM_ELEMS * 2)
#define ONES2 0x3C003C00u

__global__ __launch_bounds__(128, 2) void flash_kernel(const fp16* __restrict__ q_,
                                                       const fp16* __restrict__ k_, const fp16* __restrict__ v_,
                                                       const float* __restrict__ lng, const float* __restrict__ lnb,
                                                       fp16* __restrict__ o_) {
    extern __shared__ fp16 sm[];
    const int tid = threadIdx.x, lane = tid & 31, wid = tid >> 5;
    const int b = blockIdx.z, hp = blockIdx.y;
    const int q0 = blockIdx.x * 64;
    const int wrow = wid * 16;
    const float lam = g_lambda;

    auto copy_kv = [&](int kt, int bu) {
        int base = KVB + bu * 17408;
#pragma unroll
        for (int j = 0; j < 8; ++j) {
            int ch = tid + j * 128;
            int r = ch >> 4, s = (ch & 15) * 8;
            size_t src = (size_t)(b * NN + kt + r) * EE + hp * 128 + s;
            cpa16(s2u(&sm[base + r * 136 + s]), &k_[src]);
            cpa16(s2u(&sm[base + 8704 + r * 136 + s]), &v_[src]);
        }
    };

    // Q tile: 64 rows x 128 cols = 8192 elems -> 8 iters x 128 thr x 8 elems (own group)
#pragma unroll
    for (int j = 0; j < 8; ++j) {
        int ch = tid + j * 128;
        int r = ch >> 4, s = (ch & 15) * 8;
        size_t src = (size_t)(b * NN + q0 + r) * EE + hp * 128 + s;
        cpa16(s2u(&sm[SQ + r * 136 + s]), &q_[src]);
    }
    CP_COMMIT;
    copy_kv(0, 0);
    CP_COMMIT;

    // Q group done (KV0 may still be in flight); hoist Q fragments to registers
    CP_WAIT1;
    __syncthreads();
    uint32_t qreg[2][4][4];
#pragma unroll
    for (int half = 0; half < 2; ++half)
#pragma unroll
        for (int kg = 0; kg < 4; ++kg) {
            int d0 = half * 64 + kg * 16 + (lane >> 4) * 8;
            ldsm4(qreg[half][kg], s2u(&sm[SQ + (wrow + (lane & 15)) * 136 + d0]));
        }

    float acc0[16][4], acc1[16][4];
    float acS[2][4];   // row-sum accumulators: [half][0]=rowA, [half][2]=rowB
#pragma unroll
    for (int i = 0; i < 16; ++i)
#pragma unroll
        for (int j = 0; j < 4; ++j) { acc0[i][j] = 0.f; acc1[i][j] = 0.f; }
#pragma unroll
    for (int h2 = 0; h2 < 2; ++h2)
#pragma unroll
        for (int j = 0; j < 4; ++j) acS[h2][j] = 0.f;
    float mA[2], mB[2];
    mA[0] = mA[1] = mB[0] = mB[1] = -1e30f;

    int bu = 0;
    for (int kt = 0; kt < NN; kt += 64, bu ^= 1) {
        CP_WAIT0;
        __syncthreads();
        if (kt + 64 < NN) copy_kv(kt + 64, bu ^ 1);
        CP_COMMIT;
        const int lb = KVB + bu * 17408;

        uint32_t ph[2][4][4];
#pragma unroll
        for (int half = 0; half < 2; ++half) {
            float (*ac)[4] = half ? acc1 : acc0;
            float S[8][4];
#pragma unroll
            for (int i = 0; i < 8; ++i)
#pragma unroll
                for (int j = 0; j < 4; ++j) S[i][j] = 0.f;

            // S = Q * K over d = half*64 .. +64 (log2e and D^-0.5 pre-folded into q)
#pragma unroll
            for (int kg = 0; kg < 4; ++kg) {
                int d0 = half * 64 + kg * 16 + (lane >> 4) * 8;
#pragma unroll
                for (int p = 0; p < 4; ++p) {
                    uint32_t t[4];
                    ldsm4(t, s2u(&sm[lb + (p * 16 + (lane & 15)) * 136 + d0]));
                    mma16816(S[2 * p], qreg[half][kg], t[0], t[2]);
                    mma16816(S[2 * p + 1], qreg[half][kg], t[1], t[3]);
                }
            }

            // online softmax, exp2 domain (rows: A = lane>>2, B = +8)
            float mxA = -1e30f, mxB = -1e30f;
#pragma unroll
            for (int ng = 0; ng < 8; ++ng) {
                mxA = fmaxf(mxA, fmaxf(S[ng][0], S[ng][1]));
                mxB = fmaxf(mxB, fmaxf(S[ng][2], S[ng][3]));
            }
            mxA = fmaxf(mxA, __shfl_xor_sync(0xffffffffu, mxA, 1));
            mxA = fmaxf(mxA, __shfl_xor_sync(0xffffffffu, mxA, 2));
            mxB = fmaxf(mxB, __shfl_xor_sync(0xffffffffu, mxB, 1));
            mxB = fmaxf(mxB, __shfl_xor_sync(0xffffffffu, mxB, 2));
            float nmA = fmaxf(mA[half], mxA), nmB = fmaxf(mB[half], mxB);
            float aA = ex2(mA[half] - nmA), aB = ex2(mB[half] - nmB);
            mA[half] = nmA; mB[half] = nmB;
            // rescale accumulators only if some lane's max moved (exact identity otherwise)
            bool skip = __all_sync(0xffffffffu, (aA == 1.f) && (aB == 1.f));
            if (!skip) {
#pragma unroll
                for (int ng = 0; ng < 16; ++ng) {
                    ac[ng][0] *= aA; ac[ng][1] *= aA;
                    ac[ng][2] *= aB; ac[ng][3] *= aB;
                }
                acS[half][0] *= aA; acS[half][1] *= aA;
                acS[half][2] *= aB; acS[half][3] *= aB;
            }
            // P fragments: fused subtract + pack + exp2 in fp16x2
#pragma unroll
            for (int j = 0; j < 4; ++j) {
                ph[half][j][0] = exp2pack(S[2 * j][0] - nmA, S[2 * j][1] - nmA);
                ph[half][j][1] = exp2pack(S[2 * j][2] - nmB, S[2 * j][3] - nmB);
                ph[half][j][2] = exp2pack(S[2 * j + 1][0] - nmA, S[2 * j + 1][1] - nmA);
                ph[half][j][3] = exp2pack(S[2 * j + 1][2] - nmB, S[2 * j + 1][3] - nmB);
            }
            // row sums via all-ones B fragment (tensor core does the reduction)
#pragma unroll
            for (int j = 0; j < 4; ++j)
                mma16816(acS[half], ph[half][j], ONES2, ONES2);
        }

        // PV for both halves; V fragments loaded once
#pragma unroll
        for (int kg2 = 0; kg2 < 4; ++kg2) {
#pragma unroll
            for (int np = 0; np < 8; ++np) {
                uint32_t vf[4];
                int off = lb + 8704 + (kg2 * 16 + (lane & 15)) * 136 + np * 16 + (lane >> 4) * 8;
                ldsm4t(vf, s2u(&sm[off]));
                mma16816(acc0[2 * np], ph[0][kg2], vf[0], vf[1]);
                mma16816(acc0[2 * np + 1], ph[0][kg2], vf[2], vf[3]);
                mma16816(acc1[2 * np], ph[1][kg2], vf[0], vf[1]);
                mma16816(acc1[2 * np + 1], ph[1][kg2], vf[2], vf[3]);
            }
        }
    }

    // Epilogue: o = acc0/l0 - lam*acc1/l1, per-head LayerNorm over 128 channels.
    float i0A = 1.f / acS[0][0], i0B = 1.f / acS[0][2];
    float i1A = lam / acS[1][0], i1B = lam / acS[1][2];
    float suA = 0.f, sqA = 0.f, suB = 0.f, sqB = 0.f;
#pragma unroll
    for (int ng = 0; ng < 16; ++ng) {
        float o0 = acc0[ng][0] * i0A - acc1[ng][0] * i1A;
        float o1 = acc0[ng][1] * i0A - acc1[ng][1] * i1A;
        float o2 = acc0[ng][2] * i0B - acc1[ng][2] * i1B;
        float o3 = acc0[ng][3] * i0B - acc1[ng][3] * i1B;
        acc0[ng][0] = o0; acc0[ng][1] = o1; acc0[ng][2] = o2; acc0[ng][3] = o3;
        suA += o0 + o1; sqA += o0 * o0 + o1 * o1;
        suB += o2 + o3; sqB += o2 * o2 + o3 * o3;
    }
    suA += __shfl_xor_sync(0xffffffffu, suA, 1); suA += __shfl_xor_sync(0xffffffffu, suA, 2);
    sqA += __shfl_xor_sync(0xffffffffu, sqA, 1); sqA += __shfl_xor_sync(0xffffffffu, sqA, 2);
    suB += __shfl_xor_sync(0xffffffffu, suB, 1); suB += __shfl_xor_sync(0xffffffffu, suB, 2);
    sqB += __shfl_xor_sync(0xffffffffu, sqB, 1); sqB += __shfl_xor_sync(0xffffffffu, sqB, 2);
    float muA = suA * (1.f / 128.f), muB = suB * (1.f / 128.f);
    float rsA = rsqrtf(sqA * (1.f / 128.f) - muA * muA + 1e-5f);
    float rsB = rsqrtf(sqB * (1.f / 128.f) - muB * muB + 1e-5f);

    int rA = b * NN + q0 + wrow + (lane >> 2);
    int rB = rA + 8;
#pragma unroll
    for (int ng = 0; ng < 16; ++ng) {
        int col = ng * 8 + 2 * (lane & 3);
        float g0 = lng[col], g1 = lng[col + 1];
        float b0 = lnb[col], b1 = lnb[col + 1];
        float y0 = (acc0[ng][0] - muA) * rsA * g0 + b0;
        float y1 = (acc0[ng][1] - muA) * rsA * g1 + b1;
        float y2 = (acc0[ng][2] - muB) * rsB * g0 + b0;
        float y3 = (acc0[ng][3] - muB) * rsB * g1 + b1;
        size_t dA = (size_t)rA * EE + hp * 128 + col;
        size_t dB = (size_t)rB * EE + hp * 128 + col;
        *(uint32_t*)&o_[dA] = pack2h(y0, y1);
        *(uint32_t*)&o_[dB] = pack2h(y2, y3);
    }
}

// ---------------------------------------------------------------------------
extern "C" void kernel_launch(void* const* d_in, const int* in_sizes, int n_in,
                              void* d_out, int out_size) {
    const float* x   = (const float*)d_in[0];
    const float* Wq  = (const float*)d_in[1];
    const float* Wk  = (const float*)d_in[2];
    const float* Wv  = (const float*)d_in[3];
    const float* Wo  = (const float*)d_in[4];
    const float* lq1 = (const float*)d_in[5];
    const float* lk1 = (const float*)d_in[6];
    const float* lq2 = (const float*)d_in[7];
    const float* lk2 = (const float*)d_in[8];
    const float* lng = (const float*)d_in[9];
    const float* lnb = (const float*)d_in[10];
    float* out = (float*)d_out;

    fp16 *wqkvh, *wqkvl, *woh, *wol, *x16, *qq, *kk, *vv, *a16;
    cudaGetSymbolAddress((void**)&wqkvh, g_wqkvh);
    cudaGetSymbolAddress((void**)&wqkvl, g_wqkvl);
    cudaGetSymbolAddress((void**)&woh, g_woh);
    cudaGetSymbolAddress((void**)&wol, g_wol);
    cudaGetSymbolAddress((void**)&x16, g_x16);
    cudaGetSymbolAddress((void**)&qq, g_q);
    cudaGetSymbolAddress((void**)&kk, g_k);
    cudaGetSymbolAddress((void**)&vv, g_v);
    cudaGetSymbolAddress((void**)&a16, g_a16);

    wsplit_kernel<<<dim3(1024, 4), 256>>>(Wq, Wk, Wv, Wo);
    xround_kernel<<<4096, 256>>>(x);
    lambda_kernel<<<1, 32>>>(lq1, lk1, lq2, lk2);

    cudaFuncSetAttribute(qkv_gemm, cudaFuncAttributeMaxDynamicSharedMemorySize, GSM_BYTES);
    cudaFuncSetAttribute(out_gemm, cudaFuncAttributeMaxDynamicSharedMemorySize, GSM_BYTES);
    cudaFuncSetAttribute(flash_kernel, cudaFuncAttributeMaxDynamicSharedMemorySize, FSM_BYTES);

    const float LOG2E = 1.4426950408889634f;
    qkv_gemm<<<dim3(24, 32), 256, GSM_BYTES>>>(x16, wqkvh, wqkvl, qq, kk, vv, 0.125f * LOG2E);

    dim3 fg(NN / 64, HH, BB);  // (32, 8, 2)
    flash_kernel<<<fg, 128, FSM_BYTES>>>(qq, kk, vv, lng, lnb, a16);

    out_gemm<<<dim3(8, 32), 256, GSM_BYTES>>>(a16, woh, wol, out);
}

// round 14
// speedup vs baseline: 1.0861x; 1.0861x over previous
#include <cuda_runtime.h>
#include <cuda_fp16.h>
#include <math.h>
#include <stdint.h>

#define BB 2
#define NN 2048
#define EE 1024
#define HH 8
#define DD 64
#define MM (BB*NN)
#define N3 (3*EE)

typedef __half fp16;

// ---------------- scratch (__device__ globals; no runtime alloc) ----------------
__device__ fp16 g_wqkvh[(size_t)EE * N3];   // [k=1024][n=3072] hi  (Wq|Wk|Wv)
__device__ fp16 g_wqkvl[(size_t)EE * N3];   // lo (v section unused)
__device__ fp16 g_woh[(size_t)EE * EE], g_wol[(size_t)EE * EE];
__device__ fp16 g_x16[MM * EE];
__device__ fp16 g_q[MM * EE];               // single-rounded q (alpha pre-applied)
__device__ fp16 g_k[MM * EE];
__device__ fp16 g_v[MM * EE];
__device__ fp16 g_a16[MM * EE];
__device__ float g_lambda;

// ---------------- helpers ----------------
__device__ __forceinline__ uint32_t s2u(const void* p) {
    return (uint32_t)__cvta_generic_to_shared(p);
}
__device__ __forceinline__ void ldsm4(uint32_t* r, uint32_t a) {
    asm volatile("ldmatrix.sync.aligned.m8n8.x4.shared.b16 {%0,%1,%2,%3},[%4];\n"
                 : "=r"(r[0]), "=r"(r[1]), "=r"(r[2]), "=r"(r[3]) : "r"(a));
}
__device__ __forceinline__ void ldsm4t(uint32_t* r, uint32_t a) {
    asm volatile("ldmatrix.sync.aligned.m8n8.x4.trans.shared.b16 {%0,%1,%2,%3},[%4];\n"
                 : "=r"(r[0]), "=r"(r[1]), "=r"(r[2]), "=r"(r[3]) : "r"(a));
}
__device__ __forceinline__ void mma16816(float* d, const uint32_t* a, uint32_t b0, uint32_t b1) {
    asm volatile("mma.sync.aligned.m16n8k16.row.col.f32.f16.f16.f32 "
                 "{%0,%1,%2,%3},{%4,%5,%6,%7},{%8,%9},{%0,%1,%2,%3};\n"
                 : "+f"(d[0]), "+f"(d[1]), "+f"(d[2]), "+f"(d[3])
                 : "r"(a[0]), "r"(a[1]), "r"(a[2]), "r"(a[3]), "r"(b0), "r"(b1));
}
__device__ __forceinline__ void cpa16(uint32_t dst, const void* src) {
    asm volatile("cp.async.cg.shared.global [%0], [%1], 16;\n" :: "r"(dst), "l"(src));
}
#define CP_COMMIT asm volatile("cp.async.commit_group;\n")
#define CP_WAIT0  asm volatile("cp.async.wait_group 0;\n")
#define CP_WAIT1  asm volatile("cp.async.wait_group 1;\n")
__device__ __forceinline__ float ex2(float x) {
    float y; asm("ex2.approx.f32 %0,%1;\n" : "=f"(y) : "f"(x)); return y;
}
// pack (a -> lo, b -> hi) to fp16x2 and take exp2 of both halves in one MUFU op
__device__ __forceinline__ uint32_t exp2pack(float a, float b) {
    uint32_t p;
    asm("cvt.rn.f16x2.f32 %0, %1, %2;\n" : "=r"(p) : "f"(b), "f"(a));
    asm("ex2.approx.f16x2 %0, %0;\n" : "+r"(p));
    return p;
}
__device__ __forceinline__ void split2h(float a, float b, uint32_t& hi, uint32_t& lo) {
    __half2 h, l;
    h.x = __float2half_rn(a); h.y = __float2half_rn(b);
    l.x = __float2half_rn(a - __half2float(h.x));
    l.y = __float2half_rn(b - __half2float(h.y));
    hi = *(uint32_t*)&h; lo = *(uint32_t*)&l;
}
__device__ __forceinline__ uint32_t pack2h(float a, float b) {
    __half2 h; h.x = __float2half_rn(a); h.y = __float2half_rn(b);
    return *(uint32_t*)&h;
}

// ---------------- lambda ----------------
__global__ void lambda_kernel(const float* __restrict__ lq1, const float* __restrict__ lk1,
                              const float* __restrict__ lq2, const float* __restrict__ lk2) {
    int t = threadIdx.x;
    float s1 = 0.f, s2 = 0.f;
    for (int i = t; i < DD; i += 32) { s1 += lq1[i] * lk1[i]; s2 += lq2[i] * lk2[i]; }
#pragma unroll
    for (int o = 16; o; o >>= 1) {
        s1 += __shfl_xor_sync(0xffffffffu, s1, o);
        s2 += __shfl_xor_sync(0xffffffffu, s2, o);
    }
    if (t == 0) {
        double lam_init = 0.8 - 0.6 * exp(-0.3 * 12.0);
        g_lambda = expf(s1) - expf(s2) + (float)lam_init;
    }
}

// ---------------- weight split: Wq|Wk|Wv -> fused [1024][3072] pair; Wo -> [1024][1024] pair ----------------
__global__ void wsplit_kernel(const float* __restrict__ W0, const float* __restrict__ W1,
                              const float* __restrict__ W2, const float* __restrict__ W3) {
    int m = blockIdx.y;  // 0..3
    const float* W = (m == 0) ? W0 : (m == 1) ? W1 : (m == 2) ? W2 : W3;
    size_t i = (size_t)blockIdx.x * 1024 + threadIdx.x * 4;
    float4 v = *(const float4*)&W[i];
    uint32_t h0, l0, h1, l1;
    split2h(v.x, v.y, h0, l0);
    split2h(v.z, v.w, h1, l1);
    size_t r = i >> 10, c = i & 1023;
    uint32_t *oh, *ol;
    if (m < 3) {
        size_t d = r * N3 + m * EE + c;
        oh = (uint32_t*)&g_wqkvh[d]; ol = (uint32_t*)&g_wqkvl[d];
    } else {
        oh = (uint32_t*)&g_woh[i]; ol = (uint32_t*)&g_wol[i];
    }
    oh[0] = h0; oh[1] = h1; ol[0] = l0; ol[1] = l1;
}

__global__ void xround_kernel(const float* __restrict__ x) {
    size_t i = (size_t)blockIdx.x * 1024 + threadIdx.x * 4;
    float4 v = *(const float4*)&x[i];
    uint32_t* o = (uint32_t*)&g_x16[i];
    o[0] = pack2h(v.x, v.y);
    o[1] = pack2h(v.z, v.w);
}

// ============ shared GEMM mainloop (BK=64, 128x128 CTA tile) ============
// USELO: uniform bool; when false, skips the weight-lo copies and MMAs (1-term GEMM).
// smem layout (fp16 elems), per buf (stride 26624): A 128x64 pitch 72 at +0 (9216),
// Bh 64x128 pitch 136 at +9216 (8704), Bl at +17920 (8704). 2 bufs = 53248 elems.
#define GSM_ELEMS 53248
#define GSM_BYTES (GSM_ELEMS * 2)

#define GEMM_MAINLOOP(LDW, USELO)                                                            \
    float acc[4][4][4];                                                                       \
    _Pragma("unroll") for (int i = 0; i < 4; ++i)                                             \
        _Pragma("unroll") for (int j = 0; j < 4; ++j)                                         \
            _Pragma("unroll") for (int q = 0; q < 4; ++q) acc[i][j][q] = 0.f;                 \
    auto copy_tile = [&](int kt, int bu) {                                                    \
        int base = bu * 26624;                                                                \
        _Pragma("unroll") for (int j = 0; j < 4; ++j) {                                       \
            int ch = tid + j * 256;                                                           \
            int r = ch >> 3, s = (ch & 7) * 8;                                                \
            cpa16(s2u(&sg[base + r * 72 + s]), &A[(size_t)(m0 + r) * EE + kt + s]);           \
        }                                                                                     \
        _Pragma("unroll") for (int j = 0; j < 4; ++j) {                                       \
            int ch = tid + j * 256;                                                           \
            int r = ch >> 4, s = (ch & 15) * 8;                                               \
            cpa16(s2u(&sg[base + 9216 + r * 136 + s]), &Wh[(size_t)(kt + r) * (LDW) + n0 + s]); \
            if (USELO)                                                                        \
                cpa16(s2u(&sg[base + 17920 + r * 136 + s]), &Wl[(size_t)(kt + r) * (LDW) + n0 + s]); \
        }                                                                                     \
    };                                                                                        \
    copy_tile(0, 0);                                                                          \
    CP_COMMIT;                                                                                \
    int bu = 0;                                                                               \
    for (int kt = 0; kt < EE; kt += 64, bu ^= 1) {                                            \
        CP_WAIT0;                                                                             \
        __syncthreads();                                                                      \
        if (kt + 64 < EE) copy_tile(kt + 64, bu ^ 1);                                         \
        CP_COMMIT;                                                                            \
        int ao = bu * 26624, bo = ao + 9216;                                                  \
        _Pragma("unroll") for (int kg = 0; kg < 4; ++kg) {                                    \
            uint32_t ah[4][4], bh[4][2], bl[4][2];                                            \
            _Pragma("unroll") for (int i = 0; i < 4; ++i) {                                   \
                int off = (wm + i * 16 + (lane & 15)) * 72 + kg * 16 + (lane >> 4) * 8;       \
                ldsm4(ah[i], s2u(&sg[ao + off]));                                             \
            }                                                                                 \
            _Pragma("unroll") for (int p = 0; p < 2; ++p) {                                   \
                int off = (kg * 16 + (lane & 15)) * 136 + wn + p * 16 + (lane >> 4) * 8;      \
                uint32_t t[4], u[4];                                                          \
                ldsm4t(t, s2u(&sg[bo + off]));                                                \
                if (USELO) ldsm4t(u, s2u(&sg[bo + 8704 + off]));                              \
                else { u[0] = u[1] = u[2] = u[3] = 0; }                                       \
                bh[2 * p][0] = t[0]; bh[2 * p][1] = t[1];                                     \
                bh[2 * p + 1][0] = t[2]; bh[2 * p + 1][1] = t[3];                             \
                bl[2 * p][0] = u[0]; bl[2 * p][1] = u[1];                                     \
                bl[2 * p + 1][0] = u[2]; bl[2 * p + 1][1] = u[3];                             \
            }                                                                                 \
            _Pragma("unroll") for (int i = 0; i < 4; ++i)                                     \
                _Pragma("unroll") for (int ni = 0; ni < 4; ++ni) {                            \
                    mma16816(acc[i][ni], ah[i], bh[ni][0], bh[ni][1]);                        \
                    if (USELO) mma16816(acc[i][ni], ah[i], bl[ni][0], bl[ni][1]);             \
                }                                                                             \
        }                                                                                     \
    }

// ---------------- fused QKV GEMM: C[4096,3072] = x16 @ W; q,k use 2-term, v 1-term ----------------
__global__ __launch_bounds__(256, 2) void qkv_gemm(const fp16* __restrict__ A,
                                                   const fp16* __restrict__ Wh, const fp16* __restrict__ Wl,
                                                   fp16* __restrict__ Q, fp16* __restrict__ K,
                                                   fp16* __restrict__ V, float alpha_q) {
    extern __shared__ fp16 sg[];
    const int tid = threadIdx.x, lane = tid & 31, wid = tid >> 5;
    const int wm = (wid >> 2) * 64, wn = (wid & 3) * 32;
    const int m0 = blockIdx.y * 128, n0 = blockIdx.x * 128;
    const int sec = blockIdx.x >> 3;               // 0=q, 1=k, 2=v
    const bool use_lo = (sec < 2);

    GEMM_MAINLOOP(N3, use_lo)

    const int nbase = n0 - sec * EE;
    fp16* dst = (sec == 0) ? Q : (sec == 1) ? K : V;
    const float al = (sec == 0) ? alpha_q : 1.f;
#pragma unroll
    for (int mi = 0; mi < 4; ++mi) {
        int r0 = m0 + wm + mi * 16 + (lane >> 2);
        int r1 = r0 + 8;
#pragma unroll
        for (int ni = 0; ni < 4; ++ni) {
            int col = nbase + wn + ni * 8 + 2 * (lane & 3);
            *(uint32_t*)&dst[(size_t)r0 * EE + col] = pack2h(acc[mi][ni][0] * al, acc[mi][ni][1] * al);
            *(uint32_t*)&dst[(size_t)r1 * EE + col] = pack2h(acc[mi][ni][2] * al, acc[mi][ni][3] * al);
        }
    }
}

// ---------------- output GEMM: out[4096,1024] fp32 = a16 @ Woh (1-term) ----------------
__global__ __launch_bounds__(256, 2) void out_gemm(const fp16* __restrict__ A,
                                                   const fp16* __restrict__ Wh, const fp16* __restrict__ Wl,
                                                   float* __restrict__ Cf) {
    extern __shared__ fp16 sg[];
    const int tid = threadIdx.x, lane = tid & 31, wid = tid >> 5;
    const int wm = (wid >> 2) * 64, wn = (wid & 3) * 32;
    const int m0 = blockIdx.y * 128, n0 = blockIdx.x * 128;

    GEMM_MAINLOOP(EE, false)

#pragma unroll
    for (int mi = 0; mi < 4; ++mi) {
        int r0 = m0 + wm + mi * 16 + (lane >> 2);
        int r1 = r0 + 8;
#pragma unroll
        for (int ni = 0; ni < 4; ++ni) {
            int col = n0 + wn + ni * 8 + 2 * (lane & 3);
            *(float2*)&Cf[(size_t)r0 * EE + col] = make_float2(acc[mi][ni][0], acc[mi][ni][1]);
            *(float2*)&Cf[(size_t)r1 * EE + col] = make_float2(acc[mi][ni][2], acc[mi][ni][3]);
        }
    }
}

// ---------------- differential flash attention + fused LayerNorm (64-key tiles) ----------------
// CTA: (64 q-rows, head-pair hp, batch b); 4 warps x 16 rows; 64-key tiles double-buffered,
// single barrier per tile; Q fragments hoisted to registers; warp-voted rescale skip.
// smem (fp16 elems): Q 0 (64x136=8704); KV buf b at 8704+b*17408: K +0, V +8704.
#define SQ 0
#define KVB 8704
#define FSM_ELEMS (8704 + 2 * 17408)
#define FSM_BYTES (FSM_ELEMS * 2)
#define ONES2 0x3C003C00u

__global__ __launch_bounds__(128, 2) void flash_kernel(const fp16* __restrict__ q_,
                                                       const fp16* __restrict__ k_, const fp16* __restrict__ v_,
                                                       const float* __restrict__ lng, const float* __restrict__ lnb,
                                                       fp16* __restrict__ o_) {
    extern __shared__ fp16 sm[];
    const int tid = threadIdx.x, lane = tid & 31, wid = tid >> 5;
    const int b = blockIdx.z, hp = blockIdx.y;
    const int q0 = blockIdx.x * 64;
    const int wrow = wid * 16;
    const float lam = g_lambda;

    auto copy_kv = [&](int kt, int bu) {
        int base = KVB + bu * 17408;
#pragma unroll
        for (int j = 0; j < 8; ++j) {
            int ch = tid + j * 128;
            int r = ch >> 4, s = (ch & 15) * 8;
            size_t src = (size_t)(b * NN + kt + r) * EE + hp * 128 + s;
            cpa16(s2u(&sm[base + r * 136 + s]), &k_[src]);
            cpa16(s2u(&sm[base + 8704 + r * 136 + s]), &v_[src]);
        }
    };

    // Q tile: 64 rows x 128 cols = 8192 elems -> 8 iters x 128 thr x 8 elems (own group)
#pragma unroll
    for (int j = 0; j < 8; ++j) {
        int ch = tid + j * 128;
        int r = ch >> 4, s = (ch & 15) * 8;
        size_t src = (size_t)(b * NN + q0 + r) * EE + hp * 128 + s;
        cpa16(s2u(&sm[SQ + r * 136 + s]), &q_[src]);
    }
    CP_COMMIT;
    copy_kv(0, 0);
    CP_COMMIT;

    // Q group done (KV0 may still be in flight); hoist Q fragments to registers
    CP_WAIT1;
    __syncthreads();
    uint32_t qreg[2][4][4];
#pragma unroll
    for (int half = 0; half < 2; ++half)
#pragma unroll
        for (int kg = 0; kg < 4; ++kg) {
            int d0 = half * 64 + kg * 16 + (lane >> 4) * 8;
            ldsm4(qreg[half][kg], s2u(&sm[SQ + (wrow + (lane & 15)) * 136 + d0]));
        }

    float acc0[16][4], acc1[16][4];
    float acS[2][4];   // row-sum accumulators: [half][0]=rowA, [half][2]=rowB
#pragma unroll
    for (int i = 0; i < 16; ++i)
#pragma unroll
        for (int j = 0; j < 4; ++j) { acc0[i][j] = 0.f; acc1[i][j] = 0.f; }
#pragma unroll
    for (int h2 = 0; h2 < 2; ++h2)
#pragma unroll
        for (int j = 0; j < 4; ++j) acS[h2][j] = 0.f;
    float mA[2], mB[2];
    mA[0] = mA[1] = mB[0] = mB[1] = -1e30f;

    int bu = 0;
    for (int kt = 0; kt < NN; kt += 64, bu ^= 1) {
        CP_WAIT0;
        __syncthreads();
        if (kt + 64 < NN) copy_kv(kt + 64, bu ^ 1);
        CP_COMMIT;
        const int lb = KVB + bu * 17408;

        uint32_t ph[2][4][4];
#pragma unroll
        for (int half = 0; half < 2; ++half) {
            float (*ac)[4] = half ? acc1 : acc0;
            float S[8][4];
#pragma unroll
            for (int i = 0; i < 8; ++i)
#pragma unroll
                for (int j = 0; j < 4; ++j) S[i][j] = 0.f;

            // S = Q * K over d = half*64 .. +64 (log2e and D^-0.5 pre-folded into q)
#pragma unroll
            for (int kg = 0; kg < 4; ++kg) {
                int d0 = half * 64 + kg * 16 + (lane >> 4) * 8;
#pragma unroll
                for (int p = 0; p < 4; ++p) {
                    uint32_t t[4];
                    ldsm4(t, s2u(&sm[lb + (p * 16 + (lane & 15)) * 136 + d0]));
                    mma16816(S[2 * p], qreg[half][kg], t[0], t[2]);
                    mma16816(S[2 * p + 1], qreg[half][kg], t[1], t[3]);
                }
            }

            // online softmax, exp2 domain (rows: A = lane>>2, B = +8)
            float mxA = -1e30f, mxB = -1e30f;
#pragma unroll
            for (int ng = 0; ng < 8; ++ng) {
                mxA = fmaxf(mxA, fmaxf(S[ng][0], S[ng][1]));
                mxB = fmaxf(mxB, fmaxf(S[ng][2], S[ng][3]));
            }
            mxA = fmaxf(mxA, __shfl_xor_sync(0xffffffffu, mxA, 1));
            mxA = fmaxf(mxA, __shfl_xor_sync(0xffffffffu, mxA, 2));
            mxB = fmaxf(mxB, __shfl_xor_sync(0xffffffffu, mxB, 1));
            mxB = fmaxf(mxB, __shfl_xor_sync(0xffffffffu, mxB, 2));
            float nmA = fmaxf(mA[half], mxA), nmB = fmaxf(mB[half], mxB);
            float aA = ex2(mA[half] - nmA), aB = ex2(mB[half] - nmB);
            mA[half] = nmA; mB[half] = nmB;
            // rescale accumulators only if some lane's max moved (exact identity otherwise)
            bool skip = __all_sync(0xffffffffu, (aA == 1.f) && (aB == 1.f));
            if (!skip) {
#pragma unroll
                for (int ng = 0; ng < 16; ++ng) {
                    ac[ng][0] *= aA; ac[ng][1] *= aA;
                    ac[ng][2] *= aB; ac[ng][3] *= aB;
                }
                acS[half][0] *= aA; acS[half][1] *= aA;
                acS[half][2] *= aB; acS[half][3] *= aB;
            }
            // P fragments: fused subtract + pack + exp2 in fp16x2
#pragma unroll
            for (int j = 0; j < 4; ++j) {
                ph[half][j][0] = exp2pack(S[2 * j][0] - nmA, S[2 * j][1] - nmA);
                ph[half][j][1] = exp2pack(S[2 * j][2] - nmB, S[2 * j][3] - nmB);
                ph[half][j][2] = exp2pack(S[2 * j + 1][0] - nmA, S[2 * j + 1][1] - nmA);
                ph[half][j][3] = exp2pack(S[2 * j + 1][2] - nmB, S[2 * j + 1][3] - nmB);
            }
            // row sums via all-ones B fragment (tensor core does the reduction)
#pragma unroll
            for (int j = 0; j < 4; ++j)
                mma16816(acS[half], ph[half][j], ONES2, ONES2);
        }

        // PV for both halves; V fragments loaded once
#pragma unroll
        for (int kg2 = 0; kg2 < 4; ++kg2) {
#pragma unroll
            for (int np = 0; np < 8; ++np) {
                uint32_t vf[4];
                int off = lb + 8704 + (kg2 * 16 + (lane & 15)) * 136 + np * 16 + (lane >> 4) * 8;
                ldsm4t(vf, s2u(&sm[off]));
                mma16816(acc0[2 * np], ph[0][kg2], vf[0], vf[1]);
                mma16816(acc0[2 * np + 1], ph[0][kg2], vf[2], vf[3]);
                mma16816(acc1[2 * np], ph[1][kg2], vf[0], vf[1]);
                mma16816(acc1[2 * np + 1], ph[1][kg2], vf[2], vf[3]);
            }
        }
    }

    // Epilogue: o = acc0/l0 - lam*acc1/l1, per-head LayerNorm over 128 channels.
    float i0A = 1.f / acS[0][0], i0B = 1.f / acS[0][2];
    float i1A = lam / acS[1][0], i1B = lam / acS[1][2];
    float suA = 0.f, sqA = 0.f, suB = 0.f, sqB = 0.f;
#pragma unroll
    for (int ng = 0; ng < 16; ++ng) {
        float o0 = acc0[ng][0] * i0A - acc1[ng][0] * i1A;
        float o1 = acc0[ng][1] * i0A - acc1[ng][1] * i1A;
        float o2 = acc0[ng][2] * i0B - acc1[ng][2] * i1B;
        float o3 = acc0[ng][3] * i0B - acc1[ng][3] * i1B;
        acc0[ng][0] = o0; acc0[ng][1] = o1; acc0[ng][2] = o2; acc0[ng][3] = o3;
        suA += o0 + o1; sqA += o0 * o0 + o1 * o1;
        suB += o2 + o3; sqB += o2 * o2 + o3 * o3;
    }
    suA += __shfl_xor_sync(0xffffffffu, suA, 1); suA += __shfl_xor_sync(0xffffffffu, suA, 2);
    sqA += __shfl_xor_sync(0xffffffffu, sqA, 1); sqA += __shfl_xor_sync(0xffffffffu, sqA, 2);
    suB += __shfl_xor_sync(0xffffffffu, suB, 1); suB += __shfl_xor_sync(0xffffffffu, suB, 2);
    sqB += __shfl_xor_sync(0xffffffffu, sqB, 1); sqB += __shfl_xor_sync(0xffffffffu, sqB, 2);
    float muA = suA * (1.f / 128.f), muB = suB * (1.f / 128.f);
    float rsA = rsqrtf(sqA * (1.f / 128.f) - muA * muA + 1e-5f);
    float rsB = rsqrtf(sqB * (1.f / 128.f) - muB * muB + 1e-5f);

    int rA = b * NN + q0 + wrow + (lane >> 2);
    int rB = rA + 8;
#pragma unroll
    for (int ng = 0; ng < 16; ++ng) {
        int col = ng * 8 + 2 * (lane & 3);
        float g0 = lng[col], g1 = lng[col + 1];
        float b0 = lnb[col], b1 = lnb[col + 1];
        float y0 = (acc0[ng][0] - muA) * rsA * g0 + b0;
        float y1 = (acc0[ng][1] - muA) * rsA * g1 + b1;
        float y2 = (acc0[ng][2] - muB) * rsB * g0 + b0;
        float y3 = (acc0[ng][3] - muB) * rsB * g1 + b1;
        size_t dA = (size_t)rA * EE + hp * 128 + col;
        size_t dB = (size_t)rB * EE + hp * 128 + col;
        *(uint32_t*)&o_[dA] = pack2h(y0, y1);
        *(uint32_t*)&o_[dB] = pack2h(y2, y3);
    }
}

// ---------------------------------------------------------------------------
extern "C" void kernel_launch(void* const* d_in, const int* in_sizes, int n_in,
                              void* d_out, int out_size) {
    const float* x   = (const float*)d_in[0];
    const float* Wq  = (const float*)d_in[1];
    const float* Wk  = (const float*)d_in[2];
    const float* Wv  = (const float*)d_in[3];
    const float* Wo  = (const float*)d_in[4];
    const float* lq1 = (const float*)d_in[5];
    const float* lk1 = (const float*)d_in[6];
    const float* lq2 = (const float*)d_in[7];
    const float* lk2 = (const float*)d_in[8];
    const float* lng = (const float*)d_in[9];
    const float* lnb = (const float*)d_in[10];
    float* out = (float*)d_out;

    fp16 *wqkvh, *wqkvl, *woh, *wol, *x16, *qq, *kk, *vv, *a16;
    cudaGetSymbolAddress((void**)&wqkvh, g_wqkvh);
    cudaGetSymbolAddress((void**)&wqkvl, g_wqkvl);
    cudaGetSymbolAddress((void**)&woh, g_woh);
    cudaGetSymbolAddress((void**)&wol, g_wol);
    cudaGetSymbolAddress((void**)&x16, g_x16);
    cudaGetSymbolAddress((void**)&qq, g_q);
    cudaGetSymbolAddress((void**)&kk, g_k);
    cudaGetSymbolAddress((void**)&vv, g_v);
    cudaGetSymbolAddress((void**)&a16, g_a16);

    wsplit_kernel<<<dim3(1024, 4), 256>>>(Wq, Wk, Wv, Wo);
    xround_kernel<<<4096, 256>>>(x);
    lambda_kernel<<<1, 32>>>(lq1, lk1, lq2, lk2);

    cudaFuncSetAttribute(qkv_gemm, cudaFuncAttributeMaxDynamicSharedMemorySize, GSM_BYTES);
    cudaFuncSetAttribute(out_gemm, cudaFuncAttributeMaxDynamicSharedMemorySize, GSM_BYTES);
    cudaFuncSetAttribute(flash_kernel, cudaFuncAttributeMaxDynamicSharedMemorySize, FSM_BYTES);

    const float LOG2E = 1.4426950408889634f;
    qkv_gemm<<<dim3(24, 32), 256, GSM_BYTES>>>(x16, wqkvh, wqkvl, qq, kk, vv, 0.125f * LOG2E);

    dim3 fg(NN / 64, HH, BB);  // (32, 8, 2)
    flash_kernel<<<fg, 128, FSM_BYTES>>>(qq, kk, vv, lng, lnb, a16);

    out_gemm<<<dim3(8, 32), 256, GSM_BYTES>>>(a16, woh, wol, out);
}

// round 16
// speedup vs baseline: 1.0972x; 1.0103x over previous
#include <cuda_runtime.h>
#include <cuda_fp16.h>
#include <math.h>
#include <stdint.h>

#define BB 2
#define NN 2048
#define EE 1024
#define HH 8
#define DD 64
#define MM (BB*NN)
#define N3 (3*EE)

typedef __half fp16;

// ---------------- scratch (__device__ globals; no runtime alloc) ----------------
__device__ fp16 g_wqkvh[(size_t)EE * N3];   // [k=1024][n=3072] hi  (Wq|Wk|Wv)
__device__ fp16 g_wqkvl[(size_t)EE * N3];   // lo (only q section used)
__device__ fp16 g_woh[(size_t)EE * EE];
__device__ fp16 g_x16[MM * EE];
__device__ fp16 g_q[MM * EE];               // single-rounded q (alpha pre-applied)
__device__ fp16 g_k[MM * EE];
__device__ fp16 g_v[MM * EE];
__device__ fp16 g_a16[MM * EE];
__device__ float g_lambda;

// ---------------- helpers ----------------
__device__ __forceinline__ uint32_t s2u(const void* p) {
    return (uint32_t)__cvta_generic_to_shared(p);
}
__device__ __forceinline__ void ldsm4(uint32_t* r, uint32_t a) {
    asm volatile("ldmatrix.sync.aligned.m8n8.x4.shared.b16 {%0,%1,%2,%3},[%4];\n"
                 : "=r"(r[0]), "=r"(r[1]), "=r"(r[2]), "=r"(r[3]) : "r"(a));
}
__device__ __forceinline__ void ldsm4t(uint32_t* r, uint32_t a) {
    asm volatile("ldmatrix.sync.aligned.m8n8.x4.trans.shared.b16 {%0,%1,%2,%3},[%4];\n"
                 : "=r"(r[0]), "=r"(r[1]), "=r"(r[2]), "=r"(r[3]) : "r"(a));
}
__device__ __forceinline__ void mma16816(float* d, const uint32_t* a, uint32_t b0, uint32_t b1) {
    asm volatile("mma.sync.aligned.m16n8k16.row.col.f32.f16.f16.f32 "
                 "{%0,%1,%2,%3},{%4,%5,%6,%7},{%8,%9},{%0,%1,%2,%3};\n"
                 : "+f"(d[0]), "+f"(d[1]), "+f"(d[2]), "+f"(d[3])
                 : "r"(a[0]), "r"(a[1]), "r"(a[2]), "r"(a[3]), "r"(b0), "r"(b1));
}
__device__ __forceinline__ void cpa16(uint32_t dst, const void* src) {
    asm volatile("cp.async.cg.shared.global [%0], [%1], 16;\n" :: "r"(dst), "l"(src));
}
#define CP_COMMIT asm volatile("cp.async.commit_group;\n")
#define CP_WAIT0  asm volatile("cp.async.wait_group 0;\n")
#define CP_WAIT1  asm volatile("cp.async.wait_group 1;\n")
__device__ __forceinline__ float ex2(float x) {
    float y; asm("ex2.approx.f32 %0,%1;\n" : "=f"(y) : "f"(x)); return y;
}
// pack (a -> lo, b -> hi) to fp16x2 and take exp2 of both halves in one MUFU op
__device__ __forceinline__ uint32_t exp2pack(float a, float b) {
    uint32_t p;
    asm("cvt.rn.f16x2.f32 %0, %1, %2;\n" : "=r"(p) : "f"(b), "f"(a));
    asm("ex2.approx.f16x2 %0, %0;\n" : "+r"(p));
    return p;
}
__device__ __forceinline__ void split2h(float a, float b, uint32_t& hi, uint32_t& lo) {
    __half2 h, l;
    h.x = __float2half_rn(a); h.y = __float2half_rn(b);
    l.x = __float2half_rn(a - __half2float(h.x));
    l.y = __float2half_rn(b - __half2float(h.y));
    hi = *(uint32_t*)&h; lo = *(uint32_t*)&l;
}
__device__ __forceinline__ uint32_t pack2h(float a, float b) {
    __half2 h; h.x = __float2half_rn(a); h.y = __float2half_rn(b);
    return *(uint32_t*)&h;
}

// ---------------- lambda ----------------
__global__ void lambda_kernel(const float* __restrict__ lq1, const float* __restrict__ lk1,
                              const float* __restrict__ lq2, const float* __restrict__ lk2) {
    int t = threadIdx.x;
    float s1 = 0.f, s2 = 0.f;
    for (int i = t; i < DD; i += 32) { s1 += lq1[i] * lk1[i]; s2 += lq2[i] * lk2[i]; }
#pragma unroll
    for (int o = 16; o; o >>= 1) {
        s1 += __shfl_xor_sync(0xffffffffu, s1, o);
        s2 += __shfl_xor_sync(0xffffffffu, s2, o);
    }
    if (t == 0) {
        double lam_init = 0.8 - 0.6 * exp(-0.3 * 12.0);
        g_lambda = expf(s1) - expf(s2) + (float)lam_init;
    }
}

// ---------------- weight split: Wq|Wk|Wv -> fused [1024][3072]; lo only for q; Wo hi only ----------------
__global__ void wsplit_kernel(const float* __restrict__ W0, const float* __restrict__ W1,
                              const float* __restrict__ W2, const float* __restrict__ W3) {
    int m = blockIdx.y;  // 0..3
    const float* W = (m == 0) ? W0 : (m == 1) ? W1 : (m == 2) ? W2 : W3;
    size_t i = (size_t)blockIdx.x * 1024 + threadIdx.x * 4;
    float4 v = *(const float4*)&W[i];
    uint32_t h0, l0, h1, l1;
    split2h(v.x, v.y, h0, l0);
    split2h(v.z, v.w, h1, l1);
    size_t r = i >> 10, c = i & 1023;
    if (m < 3) {
        size_t d = r * N3 + m * EE + c;
        uint32_t* oh = (uint32_t*)&g_wqkvh[d];
        oh[0] = h0; oh[1] = h1;
        if (m == 0) {                       // lo-term kept only for Wq
            uint32_t* ol = (uint32_t*)&g_wqkvl[d];
            ol[0] = l0; ol[1] = l1;
        }
    } else {
        uint32_t* oh = (uint32_t*)&g_woh[i];
        oh[0] = h0; oh[1] = h1;
    }
}

__global__ void xround_kernel(const float* __restrict__ x) {
    size_t i = (size_t)blockIdx.x * 1024 + threadIdx.x * 4;
    float4 v = *(const float4*)&x[i];
    uint32_t* o = (uint32_t*)&g_x16[i];
    o[0] = pack2h(v.x, v.y);
    o[1] = pack2h(v.z, v.w);
}

// ============ shared GEMM mainloop (BK=64, 128x128 CTA tile) ============
// USELO: uniform bool; when false, skips the weight-lo copies and MMAs (1-term GEMM).
// smem layout (fp16 elems), per buf (stride 26624): A 128x64 pitch 72 at +0 (9216),
// Bh 64x128 pitch 136 at +9216 (8704), Bl at +17920 (8704). 2 bufs = 53248 elems.
#define GSM_ELEMS 53248
#define GSM_BYTES (GSM_ELEMS * 2)

#define GEMM_MAINLOOP(LDW, USELO)                                                            \
    float acc[4][4][4];                                                                       \
    _Pragma("unroll") for (int i = 0; i < 4; ++i)                                             \
        _Pragma("unroll") for (int j = 0; j < 4; ++j)                                         \
            _Pragma("unroll") for (int q = 0; q < 4; ++q) acc[i][j][q] = 0.f;                 \
    auto copy_tile = [&](int kt, int bu) {                                                    \
        int base = bu * 26624;                                                                \
        _Pragma("unroll") for (int j = 0; j < 4; ++j) {                                       \
            int ch = tid + j * 256;                                                           \
            int r = ch >> 3, s = (ch & 7) * 8;                                                \
            cpa16(s2u(&sg[base + r * 72 + s]), &A[(size_t)(m0 + r) * EE + kt + s]);           \
        }                                                                                     \
        _Pragma("unroll") for (int j = 0; j < 4; ++j) {                                       \
            int ch = tid + j * 256;                                                           \
            int r = ch >> 4, s = (ch & 15) * 8;                                               \
            cpa16(s2u(&sg[base + 9216 + r * 136 + s]), &Wh[(size_t)(kt + r) * (LDW) + n0 + s]); \
            if (USELO)                                                                        \
                cpa16(s2u(&sg[base + 17920 + r * 136 + s]), &Wl[(size_t)(kt + r) * (LDW) + n0 + s]); \
        }                                                                                     \
    };                                                                                        \
    copy_tile(0, 0);                                                                          \
    CP_COMMIT;                                                                                \
    int bu = 0;                                                                               \
    for (int kt = 0; kt < EE; kt += 64, bu ^= 1) {                                            \
        CP_WAIT0;                                                                             \
        __syncthreads();                                                                      \
        if (kt + 64 < EE) copy_tile(kt + 64, bu ^ 1);                                         \
        CP_COMMIT;                                                                            \
        int ao = bu * 26624, bo = ao + 9216;                                                  \
        _Pragma("unroll") for (int kg = 0; kg < 4; ++kg) {                                    \
            uint32_t ah[4][4], bh[4][2], bl[4][2];                                            \
            _Pragma("unroll") for (int i = 0; i < 4; ++i) {                                   \
                int off = (wm + i * 16 + (lane & 15)) * 72 + kg * 16 + (lane >> 4) * 8;       \
                ldsm4(ah[i], s2u(&sg[ao + off]));                                             \
            }                                                                                 \
            _Pragma("unroll") for (int p = 0; p < 2; ++p) {                                   \
                int off = (kg * 16 + (lane & 15)) * 136 + wn + p * 16 + (lane >> 4) * 8;      \
                uint32_t t[4], u[4];                                                          \
                ldsm4t(t, s2u(&sg[bo + off]));                                                \
                if (USELO) ldsm4t(u, s2u(&sg[bo + 8704 + off]));                              \
                else { u[0] = u[1] = u[2] = u[3] = 0; }                                       \
                bh[2 * p][0] = t[0]; bh[2 * p][1] = t[1];                                     \
                bh[2 * p + 1][0] = t[2]; bh[2 * p + 1][1] = t[3];                             \
                bl[2 * p][0] = u[0]; bl[2 * p][1] = u[1];                                     \
                bl[2 * p + 1][0] = u[2]; bl[2 * p + 1][1] = u[3];                             \
            }                                                                                 \
            _Pragma("unroll") for (int i = 0; i < 4; ++i)                                     \
                _Pragma("unroll") for (int ni = 0; ni < 4; ++ni) {                            \
                    mma16816(acc[i][ni], ah[i], bh[ni][0], bh[ni][1]);                        \
                    if (USELO) mma16816(acc[i][ni], ah[i], bl[ni][0], bl[ni][1]);             \
                }                                                                             \
        }                                                                                     \
    }

// ---------------- fused QKV GEMM: q 2-term; k,v 1-term; all outputs single fp16 ----------------
__global__ __launch_bounds__(256, 2) void qkv_gemm(const fp16* __restrict__ A,
                                                   const fp16* __restrict__ Wh, const fp16* __restrict__ Wl,
                                                   fp16* __restrict__ Q, fp16* __restrict__ K,
                                                   fp16* __restrict__ V, float alpha_q) {
    extern __shared__ fp16 sg[];
    const int tid = threadIdx.x, lane = tid & 31, wid = tid >> 5;
    const int wm = (wid >> 2) * 64, wn = (wid & 3) * 32;
    const int m0 = blockIdx.y * 128, n0 = blockIdx.x * 128;
    const int sec = blockIdx.x >> 3;               // 0=q, 1=k, 2=v
    const bool use_lo = (sec == 0);

    GEMM_MAINLOOP(N3, use_lo)

    const int nbase = n0 - sec * EE;
    fp16* dst = (sec == 0) ? Q : (sec == 1) ? K : V;
    const float al = (sec == 0) ? alpha_q : 1.f;
#pragma unroll
    for (int mi = 0; mi < 4; ++mi) {
        int r0 = m0 + wm + mi * 16 + (lane >> 2);
        int r1 = r0 + 8;
#pragma unroll
        for (int ni = 0; ni < 4; ++ni) {
            int col = nbase + wn + ni * 8 + 2 * (lane & 3);
            *(uint32_t*)&dst[(size_t)r0 * EE + col] = pack2h(acc[mi][ni][0] * al, acc[mi][ni][1] * al);
            *(uint32_t*)&dst[(size_t)r1 * EE + col] = pack2h(acc[mi][ni][2] * al, acc[mi][ni][3] * al);
        }
    }
}

// ---------------- output GEMM: out[4096,1024] fp32 = a16 @ Woh (1-term) ----------------
__global__ __launch_bounds__(256, 2) void out_gemm(const fp16* __restrict__ A,
                                                   const fp16* __restrict__ Wh, const fp16* __restrict__ Wl,
                                                   float* __restrict__ Cf) {
    extern __shared__ fp16 sg[];
    const int tid = threadIdx.x, lane = tid & 31, wid = tid >> 5;
    const int wm = (wid >> 2) * 64, wn = (wid & 3) * 32;
    const int m0 = blockIdx.y * 128, n0 = blockIdx.x * 128;

    GEMM_MAINLOOP(EE, false)

#pragma unroll
    for (int mi = 0; mi < 4; ++mi) {
        int r0 = m0 + wm + mi * 16 + (lane >> 2);
        int r1 = r0 + 8;
#pragma unroll
        for (int ni = 0; ni < 4; ++ni) {
            int col = n0 + wn + ni * 8 + 2 * (lane & 3);
            *(float2*)&Cf[(size_t)r0 * EE + col] = make_float2(acc[mi][ni][0], acc[mi][ni][1]);
            *(float2*)&Cf[(size_t)r1 * EE + col] = make_float2(acc[mi][ni][2], acc[mi][ni][3]);
        }
    }
}

// ---------------- differential flash attention + fused LayerNorm (64-key tiles) ----------------
// CTA: (64 q-rows, head-pair hp, batch b); 4 warps x 16 rows; 64-key tiles double-buffered,
// single barrier per tile; Q fragments hoisted to registers; warp-voted rescale skip.
// smem (fp16 elems): Q 0 (64x136=8704); KV buf b at 8704+b*17408: K +0, V +8704.
#define SQ 0
#define KVB 8704
#define FSM_ELEMS (8704 + 2 * 17408)
#define FSM_BYTES (FSM_ELEMS * 2)
#define ONES2 0x3C003C00u

__global__ __launch_bounds__(128, 2) void flash_kernel(const fp16* __restrict__ q_,
                                                       const fp16* __restrict__ k_, const fp16* __restrict__ v_,
                                                       const float* __restrict__ lng, const float* __restrict__ lnb,
                                                       fp16* __restrict__ o_) {
    extern __shared__ fp16 sm[];
    const int tid = threadIdx.x, lane = tid & 31, wid = tid >> 5;
    const int b = blockIdx.z, hp = blockIdx.y;
    const int q0 = blockIdx.x * 64;
    const int wrow = wid * 16;
    const float lam = g_lambda;

    auto copy_kv = [&](int kt, int bu) {
        int base = KVB + bu * 17408;
#pragma unroll
        for (int j = 0; j < 8; ++j) {
            int ch = tid + j * 128;
            int r = ch >> 4, s = (ch & 15) * 8;
            size_t src = (size_t)(b * NN + kt + r) * EE + hp * 128 + s;
            cpa16(s2u(&sm[base + r * 136 + s]), &k_[src]);
            cpa16(s2u(&sm[base + 8704 + r * 136 + s]), &v_[src]);
        }
    };

    // Q tile: 64 rows x 128 cols = 8192 elems -> 8 iters x 128 thr x 8 elems (own group)
#pragma unroll
    for (int j = 0; j < 8; ++j) {
        int ch = tid + j * 128;
        int r = ch >> 4, s = (ch & 15) * 8;
        size_t src = (size_t)(b * NN + q0 + r) * EE + hp * 128 + s;
        cpa16(s2u(&sm[SQ + r * 136 + s]), &q_[src]);
    }
    CP_COMMIT;
    copy_kv(0, 0);
    CP_COMMIT;

    // Q group done (KV0 may still be in flight); hoist Q fragments to registers
    CP_WAIT1;
    __syncthreads();
    uint32_t qreg[2][4][4];
#pragma unroll
    for (int half = 0; half < 2; ++half)
#pragma unroll
        for (int kg = 0; kg < 4; ++kg) {
            int d0 = half * 64 + kg * 16 + (lane >> 4) * 8;
            ldsm4(qreg[half][kg], s2u(&sm[SQ + (wrow + (lane & 15)) * 136 + d0]));
        }

    float acc0[16][4], acc1[16][4];
    float acS[2][4];   // row-sum accumulators: [half][0]=rowA, [half][2]=rowB
#pragma unroll
    for (int i = 0; i < 16; ++i)
#pragma unroll
        for (int j = 0; j < 4; ++j) { acc0[i][j] = 0.f; acc1[i][j] = 0.f; }
#pragma unroll
    for (int h2 = 0; h2 < 2; ++h2)
#pragma unroll
        for (int j = 0; j < 4; ++j) acS[h2][j] = 0.f;
    float mA[2], mB[2];
    mA[0] = mA[1] = mB[0] = mB[1] = -1e30f;

    int bu = 0;
    for (int kt = 0; kt < NN; kt += 64, bu ^= 1) {
        CP_WAIT0;
        __syncthreads();
        if (kt + 64 < NN) copy_kv(kt + 64, bu ^ 1);
        CP_COMMIT;
        const int lb = KVB + bu * 17408;

        uint32_t ph[2][4][4];
#pragma unroll
        for (int half = 0; half < 2; ++half) {
            float (*ac)[4] = half ? acc1 : acc0;
            float S[8][4];
#pragma unroll
            for (int i = 0; i < 8; ++i)
#pragma unroll
                for (int j = 0; j < 4; ++j) S[i][j] = 0.f;

            // S = Q * K over d = half*64 .. +64 (log2e and D^-0.5 pre-folded into q)
#pragma unroll
            for (int kg = 0; kg < 4; ++kg) {
                int d0 = half * 64 + kg * 16 + (lane >> 4) * 8;
#pragma unroll
                for (int p = 0; p < 4; ++p) {
                    uint32_t t[4];
                    ldsm4(t, s2u(&sm[lb + (p * 16 + (lane & 15)) * 136 + d0]));
                    mma16816(S[2 * p], qreg[half][kg], t[0], t[2]);
                    mma16816(S[2 * p + 1], qreg[half][kg], t[1], t[3]);
                }
            }

            // online softmax, exp2 domain (rows: A = lane>>2, B = +8)
            float mxA = -1e30f, mxB = -1e30f;
#pragma unroll
            for (int ng = 0; ng < 8; ++ng) {
                mxA = fmaxf(mxA, fmaxf(S[ng][0], S[ng][1]));
                mxB = fmaxf(mxB, fmaxf(S[ng][2], S[ng][3]));
            }
            mxA = fmaxf(mxA, __shfl_xor_sync(0xffffffffu, mxA, 1));
            mxA = fmaxf(mxA, __shfl_xor_sync(0xffffffffu, mxA, 2));
            mxB = fmaxf(mxB, __shfl_xor_sync(0xffffffffu, mxB, 1));
            mxB = fmaxf(mxB, __shfl_xor_sync(0xffffffffu, mxB, 2));
            float nmA = fmaxf(mA[half], mxA), nmB = fmaxf(mB[half], mxB);
            float aA = ex2(mA[half] - nmA), aB = ex2(mB[half] - nmB);
            mA[half] = nmA; mB[half] = nmB;
            // rescale accumulators only if some lane's max moved (exact identity otherwise)
            bool skip = __all_sync(0xffffffffu, (aA == 1.f) && (aB == 1.f));
            if (!skip) {
#pragma unroll
                for (int ng = 0; ng < 16; ++ng) {
                    ac[ng][0] *= aA; ac[ng][1] *= aA;
                    ac[ng][2] *= aB; ac[ng][3] *= aB;
                }
                acS[half][0] *= aA; acS[half][1] *= aA;
                acS[half][2] *= aB; acS[half][3] *= aB;
            }
            // P fragments: fused subtract + pack + exp2 in fp16x2
#pragma unroll
            for (int j = 0; j < 4; ++j) {
                ph[half][j][0] = exp2pack(S[2 * j][0] - nmA, S[2 * j][1] - nmA);
                ph[half][j][1] = exp2pack(S[2 * j][2] - nmB, S[2 * j][3] - nmB);
                ph[half][j][2] = exp2pack(S[2 * j + 1][0] - nmA, S[2 * j + 1][1] - nmA);
                ph[half][j][3] = exp2pack(S[2 * j + 1][2] - nmB, S[2 * j + 1][3] - nmB);
            }
            // row sums via all-ones B fragment (tensor core does the reduction)
#pragma unroll
            for (int j = 0; j < 4; ++j)
                mma16816(acS[half], ph[half][j], ONES2, ONES2);
        }

        // PV for both halves; V fragments loaded once
#pragma unroll
        for (int kg2 = 0; kg2 < 4; ++kg2) {
#pragma unroll
            for (int np = 0; np < 8; ++np) {
                uint32_t vf[4];
                int off = lb + 8704 + (kg2 * 16 + (lane & 15)) * 136 + np * 16 + (lane >> 4) * 8;
                ldsm4t(vf, s2u(&sm[off]));
                mma16816(acc0[2 * np], ph[0][kg2], vf[0], vf[1]);
                mma16816(acc0[2 * np + 1], ph[0][kg2], vf[2], vf[3]);
                mma16816(acc1[2 * np], ph[1][kg2], vf[0], vf[1]);
                mma16816(acc1[2 * np + 1], ph[1][kg2], vf[2], vf[3]);
            }
        }
    }

    // Epilogue: o = acc0/l0 - lam*acc1/l1, per-head LayerNorm over 128 channels.
    float i0A = 1.f / acS[0][0], i0B = 1.f / acS[0][2];
    float i1A = lam / acS[1][0], i1B = lam / acS[1][2];
    float suA = 0.f, sqA = 0.f, suB = 0.f, sqB = 0.f;
#pragma unroll
    for (int ng = 0; ng < 16; ++ng) {
        float o0 = acc0[ng][0] * i0A - acc1[ng][0] * i1A;
        float o1 = acc0[ng][1] * i0A - acc1[ng][1] * i1A;
        float o2 = acc0[ng][2] * i0B - acc1[ng][2] * i1B;
        float o3 = acc0[ng][3] * i0B - acc1[ng][3] * i1B;
        acc0[ng][0] = o0; acc0[ng][1] = o1; acc0[ng][2] = o2; acc0[ng][3] = o3;
        suA += o0 + o1; sqA += o0 * o0 + o1 * o1;
        suB += o2 + o3; sqB += o2 * o2 + o3 * o3;
    }
    suA += __shfl_xor_sync(0xffffffffu, suA, 1); suA += __shfl_xor_sync(0xffffffffu, suA, 2);
    sqA += __shfl_xor_sync(0xffffffffu, sqA, 1); sqA += __shfl_xor_sync(0xffffffffu, sqA, 2);
    suB += __shfl_xor_sync(0xffffffffu, suB, 1); suB += __shfl_xor_sync(0xffffffffu, suB, 2);
    sqB += __shfl_xor_sync(0xffffffffu, sqB, 1); sqB += __shfl_xor_sync(0xffffffffu, sqB, 2);
    float muA = suA * (1.f / 128.f), muB = suB * (1.f / 128.f);
    float rsA = rsqrtf(sqA * (1.f / 128.f) - muA * muA + 1e-5f);
    float rsB = rsqrtf(sqB * (1.f / 128.f) - muB * muB + 1e-5f);

    int rA = b * NN + q0 + wrow + (lane >> 2);
    int rB = rA + 8;
#pragma unroll
    for (int ng = 0; ng < 16; ++ng) {
        int col = ng * 8 + 2 * (lane & 3);
        float g0 = lng[col], g1 = lng[col + 1];
        float b0 = lnb[col], b1 = lnb[col + 1];
        float y0 = (acc0[ng][0] - muA) * rsA * g0 + b0;
        float y1 = (acc0[ng][1] - muA) * rsA * g1 + b1;
        float y2 = (acc0[ng][2] - muB) * rsB * g0 + b0;
        float y3 = (acc0[ng][3] - muB) * rsB * g1 + b1;
        size_t dA = (size_t)rA * EE + hp * 128 + col;
        size_t dB = (size_t)rB * EE + hp * 128 + col;
        *(uint32_t*)&o_[dA] = pack2h(y0, y1);
        *(uint32_t*)&o_[dB] = pack2h(y2, y3);
    }
}

// ---------------------------------------------------------------------------
extern "C" void kernel_launch(void* const* d_in, const int* in_sizes, int n_in,
                              void* d_out, int out_size) {
    const float* x   = (const float*)d_in[0];
    const float* Wq  = (const float*)d_in[1];
    const float* Wk  = (const float*)d_in[2];
    const float* Wv  = (const float*)d_in[3];
    const float* Wo  = (const float*)d_in[4];
    const float* lq1 = (const float*)d_in[5];
    const float* lk1 = (const float*)d_in[6];
    const float* lq2 = (const float*)d_in[7];
    const float* lk2 = (const float*)d_in[8];
    const float* lng = (const float*)d_in[9];
    const float* lnb = (const float*)d_in[10];
    float* out = (float*)d_out;

    fp16 *wqkvh, *wqkvl, *woh, *x16, *qq, *kk, *vv, *a16;
    cudaGetSymbolAddress((void**)&wqkvh, g_wqkvh);
    cudaGetSymbolAddress((void**)&wqkvl, g_wqkvl);
    cudaGetSymbolAddress((void**)&woh, g_woh);
    cudaGetSymbolAddress((void**)&x16, g_x16);
    cudaGetSymbolAddress((void**)&qq, g_q);
    cudaGetSymbolAddress((void**)&kk, g_k);
    cudaGetSymbolAddress((void**)&vv, g_v);
    cudaGetSymbolAddress((void**)&a16, g_a16);

    wsplit_kernel<<<dim3(1024, 4), 256>>>(Wq, Wk, Wv, Wo);
    xround_kernel<<<4096, 256>>>(x);
    lambda_kernel<<<1, 32>>>(lq1, lk1, lq2, lk2);

    cudaFuncSetAttribute(qkv_gemm, cudaFuncAttributeMaxDynamicSharedMemorySize, GSM_BYTES);
    cudaFuncSetAttribute(out_gemm, cudaFuncAttributeMaxDynamicSharedMemorySize, GSM_BYTES);
    cudaFuncSetAttribute(flash_kernel, cudaFuncAttributeMaxDynamicSharedMemorySize, FSM_BYTES);

    const float LOG2E = 1.4426950408889634f;
    qkv_gemm<<<dim3(24, 32), 256, GSM_BYTES>>>(x16, wqkvh, wqkvl, qq, kk, vv, 0.125f * LOG2E);

    dim3 fg(NN / 64, HH, BB);  // (32, 8, 2)
    flash_kernel<<<fg, 128, FSM_BYTES>>>(qq, kk, vv, lng, lnb, a16);

    out_gemm<<<dim3(8, 32), 256, GSM_BYTES>>>(a16, woh, nullptr, out);
}